// round 1
// baseline (speedup 1.0000x reference)
#include <cuda_runtime.h>
#include <cuda_bf16.h>
#include <math.h>

// Problem constants
#define B_      4096
#define STOCH_  1024
#define ACT_    32
#define DETER_  4096
#define T_      16
#define D_      256
#define S_      256
#define L_      4
#define KIN_    (STOCH_ + ACT_)   // 1056
#define EPS_    1e-4f

// ---------------- scratch (device globals; no allocation) ----------------
__device__ float g_tokens[B_ * T_ * D_];   // [B, T, D]
__device__ float g_x[B_ * T_ * D_];        // [B, T, D] (rmsnormed tokens)
__device__ float g_u[B_ * T_ * S_];        // [B, T, S] u, scanned in-place -> states
__device__ float g_h[B_ * D_];             // input-proj pre-norm
__device__ float g_cat[B_ * KIN_];         // concat(stoch, a_norm)

// ---------------- shift: tokens[b, 0..14, :] = deter[b, 1..15, :] --------
__global__ void shift_kernel(const float* __restrict__ deter, float* __restrict__ tokens)
{
    int idx = blockIdx.x * blockDim.x + threadIdx.x;     // over B*960 float4
    if (idx >= B_ * 960) return;
    int b = idx / 960;
    int r = idx - b * 960;
    const float4* s = reinterpret_cast<const float4*>(deter) + (size_t)b * 1024 + 64 + r;
    float4* d = reinterpret_cast<float4*>(tokens) + (size_t)b * 1024 + r;
    *d = *s;
}

// ---------------- concat(stoch, action/max(|action|,1)) ------------------
__global__ void concat_kernel(const float* __restrict__ stoch,
                              const float* __restrict__ action,
                              float* __restrict__ cat)
{
    int idx = blockIdx.x * blockDim.x + threadIdx.x;     // over B*1056
    if (idx >= B_ * KIN_) return;
    int b = idx / KIN_;
    int k = idx - b * KIN_;
    float v;
    if (k < STOCH_) {
        v = stoch[(size_t)b * STOCH_ + k];
    } else {
        float a = action[(size_t)b * ACT_ + (k - STOCH_)];
        v = a / fmaxf(fabsf(a), 1.0f);
    }
    cat[idx] = v;
}

// ---------------- generic fp32 GEMM: C = A@W^T (+A2@W2^T) + bias(+bias2) (+Cin)
// A: [M, K] row-major, W: [N=256, K] row-major. BM=BN=128, BK=8, 256 threads.
__global__ __launch_bounds__(256, 2) void gemm_tn(
    const float* __restrict__ A,  const float* __restrict__ W,
    const float* __restrict__ bias,
    const float* __restrict__ A2, const float* __restrict__ W2,
    const float* __restrict__ bias2,
    const float* __restrict__ Cin, float* __restrict__ C,
    int K1, int K2)
{
    __shared__ float As[8][128];
    __shared__ float Ws[8][128];

    const int tid = threadIdx.x;
    const int m0 = blockIdx.y * 128;
    const int n0 = blockIdx.x * 128;
    const int lr = tid >> 1;            // 0..127
    const int lc = (tid & 1) * 4;       // 0 or 4
    const int tx = tid & 15;
    const int ty = tid >> 4;

    float acc[8][8];
#pragma unroll
    for (int i = 0; i < 8; i++)
#pragma unroll
        for (int j = 0; j < 8; j++) acc[i][j] = 0.0f;

#pragma unroll 1
    for (int pass = 0; pass < 2; ++pass) {
        const float* Ap = pass ? A2 : A;
        const float* Wp = pass ? W2 : W;
        const int    K  = pass ? K2 : K1;
        if (Ap == nullptr) continue;

#pragma unroll 1
        for (int k0 = 0; k0 < K; k0 += 8) {
            float4 av = *reinterpret_cast<const float4*>(Ap + (size_t)(m0 + lr) * K + k0 + lc);
            float4 wv = *reinterpret_cast<const float4*>(Wp + (size_t)(n0 + lr) * K + k0 + lc);
            As[lc + 0][lr] = av.x; As[lc + 1][lr] = av.y;
            As[lc + 2][lr] = av.z; As[lc + 3][lr] = av.w;
            Ws[lc + 0][lr] = wv.x; Ws[lc + 1][lr] = wv.y;
            Ws[lc + 2][lr] = wv.z; Ws[lc + 3][lr] = wv.w;
            __syncthreads();
#pragma unroll
            for (int kk = 0; kk < 8; kk++) {
                float a[8], b[8];
                *reinterpret_cast<float4*>(&a[0]) = *reinterpret_cast<const float4*>(&As[kk][ty * 8 + 0]);
                *reinterpret_cast<float4*>(&a[4]) = *reinterpret_cast<const float4*>(&As[kk][ty * 8 + 4]);
                *reinterpret_cast<float4*>(&b[0]) = *reinterpret_cast<const float4*>(&Ws[kk][tx * 8 + 0]);
                *reinterpret_cast<float4*>(&b[4]) = *reinterpret_cast<const float4*>(&Ws[kk][tx * 8 + 4]);
#pragma unroll
                for (int i = 0; i < 8; i++)
#pragma unroll
                    for (int j = 0; j < 8; j++)
                        acc[i][j] = fmaf(a[i], b[j], acc[i][j]);
            }
            __syncthreads();
        }
    }

    // epilogue
    float bsum[8];
#pragma unroll
    for (int j = 0; j < 8; j++) {
        int c = n0 + tx * 8 + j;
        bsum[j] = bias[c] + (bias2 ? bias2[c] : 0.0f);
    }
#pragma unroll
    for (int i = 0; i < 8; i++) {
        int r = m0 + ty * 8 + i;
        size_t off = (size_t)r * D_ + n0 + tx * 8;
        float out[8];
        if (Cin) {
            float4 c0 = *reinterpret_cast<const float4*>(Cin + off);
            float4 c1 = *reinterpret_cast<const float4*>(Cin + off + 4);
            out[0] = acc[i][0] + bsum[0] + c0.x; out[1] = acc[i][1] + bsum[1] + c0.y;
            out[2] = acc[i][2] + bsum[2] + c0.z; out[3] = acc[i][3] + bsum[3] + c0.w;
            out[4] = acc[i][4] + bsum[4] + c1.x; out[5] = acc[i][5] + bsum[5] + c1.y;
            out[6] = acc[i][6] + bsum[6] + c1.z; out[7] = acc[i][7] + bsum[7] + c1.w;
        } else {
#pragma unroll
            for (int j = 0; j < 8; j++) out[j] = acc[i][j] + bsum[j];
        }
        *reinterpret_cast<float4*>(C + off)     = *reinterpret_cast<float4*>(&out[0]);
        *reinterpret_cast<float4*>(C + off + 4) = *reinterpret_cast<float4*>(&out[4]);
    }
}

// ---------------- warp-per-row RMSNorm (rows of 256), optional SiLU -------
__global__ void rmsnorm_rows(const float* __restrict__ in, const float* __restrict__ w,
                             float* __restrict__ out, int out_stride, int do_silu)
{
    int gwarp = (blockIdx.x * blockDim.x + threadIdx.x) >> 5;
    int lane  = threadIdx.x & 31;
    const float* rp = in + (size_t)gwarp * 256 + lane * 8;
    float v[8];
    *reinterpret_cast<float4*>(&v[0]) = *reinterpret_cast<const float4*>(rp);
    *reinterpret_cast<float4*>(&v[4]) = *reinterpret_cast<const float4*>(rp + 4);
    float s = 0.0f;
#pragma unroll
    for (int j = 0; j < 8; j++) s += v[j] * v[j];
#pragma unroll
    for (int o = 16; o > 0; o >>= 1) s += __shfl_xor_sync(0xffffffffu, s, o);
    float scale = rsqrtf(s * (1.0f / 256.0f) + EPS_);

    float wl[8];
    *reinterpret_cast<float4*>(&wl[0]) = *reinterpret_cast<const float4*>(w + lane * 8);
    *reinterpret_cast<float4*>(&wl[4]) = *reinterpret_cast<const float4*>(w + lane * 8 + 4);

    float o8[8];
#pragma unroll
    for (int j = 0; j < 8; j++) {
        float y = v[j] * scale * wl[j];
        if (do_silu) y = y / (1.0f + expf(-y));
        o8[j] = y;
    }
    float* op = out + (size_t)gwarp * out_stride + lane * 8;
    *reinterpret_cast<float4*>(op)     = *reinterpret_cast<float4*>(&o8[0]);
    *reinterpret_cast<float4*>(op + 4) = *reinterpret_cast<float4*>(&o8[4]);
}

// ---------------- scan over T=16: states = scan(decay*state + u), in place
__global__ void scan_kernel(float* __restrict__ u, const float* __restrict__ log_decay)
{
    int idx = blockIdx.x * blockDim.x + threadIdx.x;     // b*S + s
    if (idx >= B_ * S_) return;
    int s = idx & (S_ - 1);
    int b = idx >> 8;
    float d = 1.0f / (1.0f + expf(-log_decay[s]));
    float* p = u + (size_t)b * T_ * S_ + s;
    float st = 0.0f;
#pragma unroll
    for (int t = 0; t < T_; t++) {
        st = d * st + p[t * S_];
        p[t * S_] = st;
    }
}

// ---------------- launch -------------------------------------------------
extern "C" void kernel_launch(void* const* d_in, const int* in_sizes, int n_in,
                              void* d_out, int out_size)
{
    const float* stoch      = (const float*)d_in[0];
    const float* deter      = (const float*)d_in[1];
    const float* action     = (const float*)d_in[2];
    const float* W0         = (const float*)d_in[3];
    const float* b0         = (const float*)d_in[4];
    const float* g0         = (const float*)d_in[5];
    const float* norm_w     = (const float*)d_in[6];
    const float* W_in       = (const float*)d_in[7];
    const float* b_in       = (const float*)d_in[8];
    const float* W_out      = (const float*)d_in[9];
    const float* b_out      = (const float*)d_in[10];
    const float* W_skip     = (const float*)d_in[11];
    const float* b_skip     = (const float*)d_in[12];
    const float* log_decay  = (const float*)d_in[13];
    const float* out_norm_w = (const float*)d_in[14];
    float* out = (float*)d_out;

    float *tokens, *x, *u, *h, *cat;
    cudaGetSymbolAddress((void**)&tokens, g_tokens);
    cudaGetSymbolAddress((void**)&x,      g_x);
    cudaGetSymbolAddress((void**)&u,      g_u);
    cudaGetSymbolAddress((void**)&h,      g_h);
    cudaGetSymbolAddress((void**)&cat,    g_cat);

    // 1. token shift from deter
    shift_kernel<<<(B_ * 960 + 255) / 256, 256>>>(deter, tokens);

    // 2. concat(stoch, normalized action)
    concat_kernel<<<(B_ * KIN_ + 255) / 256, 256>>>(stoch, action, cat);

    // 3. input proj: h = cat @ W0^T + b0   (M=4096, K=1056, N=256)
    {
        dim3 grid(2, B_ / 128);
        gemm_tn<<<grid, 256>>>(cat, W0, b0, nullptr, nullptr, nullptr, nullptr, h, KIN_, 0);
    }

    // 4. new_tok = silu(rmsnorm(h, g0)) -> tokens[:, 15, :]
    rmsnorm_rows<<<B_ / 8, 256>>>(h, g0, tokens + 15 * D_, T_ * D_, 1);

    const int M = B_ * T_;   // 65536
    dim3 grid_big(2, M / 128);

    // 5. S4 layers
    for (int l = 0; l < L_; l++) {
        const float* nw  = norm_w    + (size_t)l * D_;
        const float* Wi  = W_in      + (size_t)l * S_ * D_;
        const float* bi  = b_in      + (size_t)l * S_;
        const float* Wo  = W_out     + (size_t)l * D_ * S_;
        const float* bo  = b_out     + (size_t)l * D_;
        const float* Ws  = W_skip    + (size_t)l * D_ * D_;
        const float* bsk = b_skip    + (size_t)l * D_;
        const float* ld  = log_decay + (size_t)l * S_;

        // x = rmsnorm(tokens, nw)
        rmsnorm_rows<<<M / 8, 256>>>(tokens, nw, x, D_, 0);

        // u = x @ W_in^T + b_in
        gemm_tn<<<grid_big, 256>>>(x, Wi, bi, nullptr, nullptr, nullptr, nullptr, u, S_, 0);

        // states = scan(u) in place
        scan_kernel<<<(B_ * S_ + 255) / 256, 256>>>(u, ld);

        // tokens += states @ W_out^T + b_out + x @ W_skip^T + b_skip
        gemm_tn<<<grid_big, 256>>>(u, Wo, bo, x, Ws, bsk, tokens, tokens, S_, D_);
    }

    // 6. final rmsnorm -> output
    rmsnorm_rows<<<M / 8, 256>>>(tokens, out_norm_w, out, D_, 0);
}

// round 2
// speedup vs baseline: 1.5667x; 1.5667x over previous
#include <cuda_runtime.h>
#include <cuda_bf16.h>
#include <math.h>

// Problem constants
#define B_      4096
#define STOCH_  1024
#define ACT_    32
#define DETER_  4096
#define T_      16
#define D_      256
#define S_      256
#define L_      4
#define KIN_    (STOCH_ + ACT_)   // 1056
#define EPS_    1e-4f
#define M_BIG   (B_ * T_)         // 65536

// ---------------- scratch (device globals; no allocation) ----------------
__device__ float g_tokA[M_BIG * D_];      // token buffer A
__device__ float g_tokB[M_BIG * D_];      // token buffer B (ping-pong)
__device__ float g_states[M_BIG * S_];    // u -> states
__device__ float g_h[B_ * D_];            // input-proj pre-norm
__device__ float g_cat[B_ * KIN_];        // concat(stoch, a_norm)
__device__ float g_scales[M_BIG];         // per-row rms scales

// ---------------- helpers -------------------------------------------------
__device__ __forceinline__ unsigned f2tf32(float x) {
    unsigned r;
    asm("cvt.rna.tf32.f32 %0, %1;" : "=r"(r) : "f"(x));
    return r;
}

__device__ __forceinline__ void mma_tf32(float* c, const unsigned* a, const unsigned* b) {
    asm volatile(
        "mma.sync.aligned.m16n8k8.row.col.f32.tf32.tf32.f32 "
        "{%0,%1,%2,%3}, {%4,%5,%6,%7}, {%8,%9}, {%0,%1,%2,%3};"
        : "+f"(c[0]), "+f"(c[1]), "+f"(c[2]), "+f"(c[3])
        : "r"(a[0]), "r"(a[1]), "r"(a[2]), "r"(a[3]), "r"(b[0]), "r"(b[1]));
}

// ---------------- shift: tokens[b, 0..14, :] = deter[b, 1..15, :] --------
__global__ void shift_kernel(const float* __restrict__ deter, float* __restrict__ tokens)
{
    int idx = blockIdx.x * blockDim.x + threadIdx.x;     // over B*960 float4
    if (idx >= B_ * 960) return;
    int b = idx / 960;
    int r = idx - b * 960;
    const float4* s = reinterpret_cast<const float4*>(deter) + (size_t)b * 1024 + 64 + r;
    float4* d = reinterpret_cast<float4*>(tokens) + (size_t)b * 1024 + r;
    *d = *s;
}

// ---------------- concat(stoch, action/max(|action|,1)) ------------------
__global__ void concat_kernel(const float* __restrict__ stoch,
                              const float* __restrict__ action,
                              float* __restrict__ cat)
{
    int idx = blockIdx.x * blockDim.x + threadIdx.x;     // over B*1056
    if (idx >= B_ * KIN_) return;
    int b = idx / KIN_;
    int k = idx - b * KIN_;
    float v;
    if (k < STOCH_) {
        v = stoch[(size_t)b * STOCH_ + k];
    } else {
        float a = action[(size_t)b * ACT_ + (k - STOCH_)];
        v = a / fmaxf(fabsf(a), 1.0f);
    }
    cat[idx] = v;
}

// ---------------- per-row rms scale: scales[m] = rsqrt(mean(row^2)+eps) ---
__global__ void scale_kernel(const float* __restrict__ in, float* __restrict__ scales)
{
    int gwarp = (blockIdx.x * blockDim.x + threadIdx.x) >> 5;
    int lane  = threadIdx.x & 31;
    const float* rp = in + (size_t)gwarp * 256 + lane * 8;
    float v[8];
    *reinterpret_cast<float4*>(&v[0]) = *reinterpret_cast<const float4*>(rp);
    *reinterpret_cast<float4*>(&v[4]) = *reinterpret_cast<const float4*>(rp + 4);
    float s = 0.0f;
#pragma unroll
    for (int j = 0; j < 8; j++) s += v[j] * v[j];
#pragma unroll
    for (int o = 16; o > 0; o >>= 1) s += __shfl_xor_sync(0xffffffffu, s, o);
    if (lane == 0) scales[gwarp] = rsqrtf(s * (1.0f / 256.0f) + EPS_);
}

// ---------------- warp-per-row RMSNorm (rows of 256), optional SiLU -------
__global__ void rmsnorm_rows(const float* __restrict__ in, const float* __restrict__ w,
                             float* __restrict__ out, int out_stride, int do_silu)
{
    int gwarp = (blockIdx.x * blockDim.x + threadIdx.x) >> 5;
    int lane  = threadIdx.x & 31;
    const float* rp = in + (size_t)gwarp * 256 + lane * 8;
    float v[8];
    *reinterpret_cast<float4*>(&v[0]) = *reinterpret_cast<const float4*>(rp);
    *reinterpret_cast<float4*>(&v[4]) = *reinterpret_cast<const float4*>(rp + 4);
    float s = 0.0f;
#pragma unroll
    for (int j = 0; j < 8; j++) s += v[j] * v[j];
#pragma unroll
    for (int o = 16; o > 0; o >>= 1) s += __shfl_xor_sync(0xffffffffu, s, o);
    float scale = rsqrtf(s * (1.0f / 256.0f) + EPS_);

    float wl[8];
    *reinterpret_cast<float4*>(&wl[0]) = *reinterpret_cast<const float4*>(w + lane * 8);
    *reinterpret_cast<float4*>(&wl[4]) = *reinterpret_cast<const float4*>(w + lane * 8 + 4);

    float o8[8];
#pragma unroll
    for (int j = 0; j < 8; j++) {
        float y = v[j] * scale * wl[j];
        if (do_silu) y = y / (1.0f + expf(-y));
        o8[j] = y;
    }
    float* op = out + (size_t)gwarp * out_stride + lane * 8;
    *reinterpret_cast<float4*>(op)     = *reinterpret_cast<float4*>(&o8[0]);
    *reinterpret_cast<float4*>(op + 4) = *reinterpret_cast<float4*>(&o8[4]);
}

// ---------------- tf32 MMA mainloop (BM=64, BN=256) -----------------------
// A: [M, K] row-major (optionally normalized: a*scale[m]*nw[k]),
// W: [256, K] row-major (acts as B col-major [K, 256]).
// 8 warps: wm in {0,1} (32 rows each), wn in {0..3} (64 cols each).
__device__ __forceinline__ void mma_mainloop(
    const float* __restrict__ A, const float* __restrict__ W, int K,
    const float* __restrict__ scale, const float* __restrict__ nw,
    int m0, float acc[2][8][4],
    unsigned (*As)[65], unsigned (*Bs)[33])
{
    const int tid  = threadIdx.x;
    const int lane = tid & 31;
    const int wid  = tid >> 5;
    const int wm   = wid & 1;
    const int wn   = wid >> 1;
    const int gid  = lane >> 2;
    const int tig  = lane & 3;

    const int am = tid >> 2;             // 0..63
    const int ak = (tid & 3) * 8;        // 0,8,16,24
    const float sm = scale ? scale[m0 + am] : 1.0f;

    for (int k0 = 0; k0 < K; k0 += 32) {
        // ---- stage A tile (64 x 32), normalize inline, store tf32 [k][m]
        {
            const float* p = A + (size_t)(m0 + am) * K + k0 + ak;
            float4 v0 = *reinterpret_cast<const float4*>(p);
            float4 v1 = *reinterpret_cast<const float4*>(p + 4);
            float vv[8] = {v0.x, v0.y, v0.z, v0.w, v1.x, v1.y, v1.z, v1.w};
#pragma unroll
            for (int i = 0; i < 8; i++) {
                float f = vv[i] * sm;
                if (nw) f *= nw[k0 + ak + i];
                As[ak + i][am] = f2tf32(f);
            }
        }
        // ---- stage B tile (256 x 32), store tf32 [n][k]
        {
#pragma unroll
            for (int rr = 0; rr < 2; rr++) {
                int n  = (tid >> 1) + rr * 128;
                int kq = (tid & 1) * 16;
                const float* p = W + (size_t)n * K + k0 + kq;
#pragma unroll
                for (int q = 0; q < 4; q++) {
                    float4 v = *reinterpret_cast<const float4*>(p + q * 4);
                    Bs[n][kq + q * 4 + 0] = f2tf32(v.x);
                    Bs[n][kq + q * 4 + 1] = f2tf32(v.y);
                    Bs[n][kq + q * 4 + 2] = f2tf32(v.z);
                    Bs[n][kq + q * 4 + 3] = f2tf32(v.w);
                }
            }
        }
        __syncthreads();
        // ---- compute 4 k-steps of 8
#pragma unroll
        for (int ks = 0; ks < 4; ks++) {
            const int kb = ks * 8;
            unsigned a[2][4];
#pragma unroll
            for (int mt = 0; mt < 2; mt++) {
                int mrow = wm * 32 + mt * 16 + gid;
                a[mt][0] = As[kb + tig][mrow];
                a[mt][1] = As[kb + tig][mrow + 8];
                a[mt][2] = As[kb + tig + 4][mrow];
                a[mt][3] = As[kb + tig + 4][mrow + 8];
            }
#pragma unroll
            for (int j = 0; j < 8; j++) {
                int nb = wn * 64 + j * 8 + gid;
                unsigned b[2] = { Bs[nb][kb + tig], Bs[nb][kb + tig + 4] };
                mma_tf32(acc[0][j], a[0], b);
                mma_tf32(acc[1][j], a[1], b);
            }
        }
        __syncthreads();
    }
}

// ---------------- generic GEMM: C = A1@W1^T (+A2@W2^T) + b1 (+b2) (+Cin) --
__global__ __launch_bounds__(256, 2) void mma_gemm(
    const float* __restrict__ A1, const float* __restrict__ W1, int K1,
    const float* __restrict__ scale1, const float* __restrict__ nw1,
    const float* __restrict__ A2, const float* __restrict__ W2, int K2,
    const float* __restrict__ scale2, const float* __restrict__ nw2,
    const float* __restrict__ bias1, const float* __restrict__ bias2,
    const float* __restrict__ Cin, float* __restrict__ C)
{
    extern __shared__ unsigned smem_u[];
    unsigned (*As)[65] = reinterpret_cast<unsigned(*)[65]>(smem_u);
    unsigned (*Bs)[33] = reinterpret_cast<unsigned(*)[33]>(smem_u + 32 * 65);

    const int m0 = blockIdx.x * 64;
    float acc[2][8][4];
#pragma unroll
    for (int mt = 0; mt < 2; mt++)
#pragma unroll
        for (int j = 0; j < 8; j++)
#pragma unroll
            for (int q = 0; q < 4; q++) acc[mt][j][q] = 0.0f;

    mma_mainloop(A1, W1, K1, scale1, nw1, m0, acc, As, Bs);
    if (A2) mma_mainloop(A2, W2, K2, scale2, nw2, m0, acc, As, Bs);

    const int lane = threadIdx.x & 31;
    const int wid  = threadIdx.x >> 5;
    const int wm   = wid & 1, wn = wid >> 1;
    const int gid  = lane >> 2, tig = lane & 3;

#pragma unroll
    for (int j = 0; j < 8; j++) {
        int col = wn * 64 + j * 8 + tig * 2;
        float b0 = bias1[col]     + (bias2 ? bias2[col]     : 0.0f);
        float b1 = bias1[col + 1] + (bias2 ? bias2[col + 1] : 0.0f);
#pragma unroll
        for (int mt = 0; mt < 2; mt++) {
            int row = m0 + wm * 32 + mt * 16 + gid;
            size_t i0 = (size_t)row * 256 + col;
            size_t i1 = (size_t)(row + 8) * 256 + col;
            float2 o0, o1;
            o0.x = acc[mt][j][0] + b0; o0.y = acc[mt][j][1] + b1;
            o1.x = acc[mt][j][2] + b0; o1.y = acc[mt][j][3] + b1;
            if (Cin) {
                float2 c0 = *reinterpret_cast<const float2*>(Cin + i0);
                float2 c1 = *reinterpret_cast<const float2*>(Cin + i1);
                o0.x += c0.x; o0.y += c0.y;
                o1.x += c1.x; o1.y += c1.y;
            }
            *reinterpret_cast<float2*>(C + i0) = o0;
            *reinterpret_cast<float2*>(C + i1) = o1;
        }
    }
}

// ---------------- GEMM1 + fused scan: states = scan(x@Wi^T + bi) ----------
// BM=64 rows = 4 full batches (16 tokens each); BN=256 = full S.
__global__ __launch_bounds__(256, 2) void mma_gemm_scan(
    const float* __restrict__ A, const float* __restrict__ W,
    const float* __restrict__ scale, const float* __restrict__ nw,
    const float* __restrict__ bias, const float* __restrict__ log_decay,
    float* __restrict__ states)
{
    extern __shared__ unsigned smem_u[];
    unsigned (*As)[65] = reinterpret_cast<unsigned(*)[65]>(smem_u);
    unsigned (*Bs)[33] = reinterpret_cast<unsigned(*)[33]>(smem_u + 32 * 65);
    float (*Us)[260]   = reinterpret_cast<float(*)[260]>(smem_u);

    const int m0 = blockIdx.x * 64;
    float acc[2][8][4];
#pragma unroll
    for (int mt = 0; mt < 2; mt++)
#pragma unroll
        for (int j = 0; j < 8; j++)
#pragma unroll
            for (int q = 0; q < 4; q++) acc[mt][j][q] = 0.0f;

    mma_mainloop(A, W, 256, scale, nw, m0, acc, As, Bs);

    const int tid  = threadIdx.x;
    const int lane = tid & 31;
    const int wid  = tid >> 5;
    const int wm   = wid & 1, wn = wid >> 1;
    const int gid  = lane >> 2, tig = lane & 3;

    // u tile (+bias) into smem
#pragma unroll
    for (int j = 0; j < 8; j++) {
        int col = wn * 64 + j * 8 + tig * 2;
        float b0 = bias[col], b1 = bias[col + 1];
#pragma unroll
        for (int mt = 0; mt < 2; mt++) {
            int r = wm * 32 + mt * 16 + gid;
            Us[r][col]         = acc[mt][j][0] + b0;
            Us[r][col + 1]     = acc[mt][j][1] + b1;
            Us[r + 8][col]     = acc[mt][j][2] + b0;
            Us[r + 8][col + 1] = acc[mt][j][3] + b1;
        }
    }
    __syncthreads();

    // scan along t within each of the 4 batches, per column
#pragma unroll
    for (int rep = 0; rep < 4; rep++) {
        int task = rep * 256 + tid;
        int bb = task >> 8;
        int c  = task & 255;
        float dec = 1.0f / (1.0f + expf(-log_decay[c]));
        float st = 0.0f;
#pragma unroll
        for (int t = 0; t < 16; t++) {
            st = dec * st + Us[bb * 16 + t][c];
            Us[bb * 16 + t][c] = st;
        }
    }
    __syncthreads();

    // coalesced store of states tile
#pragma unroll
    for (int i = 0; i < 16; i++) {
        int f  = i * 256 + tid;       // float4 index within tile
        int r  = f >> 6;
        int c4 = (f & 63) * 4;
        float4 v = *reinterpret_cast<float4*>(&Us[r][c4]);
        *reinterpret_cast<float4*>(states + (size_t)(m0 + r) * 256 + c4) = v;
    }
}

// ---------------- launch -------------------------------------------------
extern "C" void kernel_launch(void* const* d_in, const int* in_sizes, int n_in,
                              void* d_out, int out_size)
{
    const float* stoch      = (const float*)d_in[0];
    const float* deter      = (const float*)d_in[1];
    const float* action     = (const float*)d_in[2];
    const float* W0         = (const float*)d_in[3];
    const float* b0         = (const float*)d_in[4];
    const float* g0         = (const float*)d_in[5];
    const float* norm_w     = (const float*)d_in[6];
    const float* W_in       = (const float*)d_in[7];
    const float* b_in       = (const float*)d_in[8];
    const float* W_out      = (const float*)d_in[9];
    const float* b_out      = (const float*)d_in[10];
    const float* W_skip     = (const float*)d_in[11];
    const float* b_skip     = (const float*)d_in[12];
    const float* log_decay  = (const float*)d_in[13];
    const float* out_norm_w = (const float*)d_in[14];
    float* out = (float*)d_out;

    float *tokA, *tokB, *states, *h, *cat, *scales;
    cudaGetSymbolAddress((void**)&tokA,   g_tokA);
    cudaGetSymbolAddress((void**)&tokB,   g_tokB);
    cudaGetSymbolAddress((void**)&states, g_states);
    cudaGetSymbolAddress((void**)&h,      g_h);
    cudaGetSymbolAddress((void**)&cat,    g_cat);
    cudaGetSymbolAddress((void**)&scales, g_scales);

    const int SMEM_GEMM = (32 * 65 + 256 * 33) * 4;   // 42112
    const int SMEM_SCAN = 64 * 260 * 4;               // 66560
    cudaFuncSetAttribute(mma_gemm_scan,
                         cudaFuncAttributeMaxDynamicSharedMemorySize, SMEM_SCAN);

    // 1. token shift + 2. concat
    shift_kernel<<<(B_ * 960 + 255) / 256, 256>>>(deter, tokA);
    concat_kernel<<<(B_ * KIN_ + 255) / 256, 256>>>(stoch, action, cat);

    // 3. input proj: h = cat @ W0^T + b0  (M=4096, K=1056)
    mma_gemm<<<B_ / 64, 256, SMEM_GEMM>>>(
        cat, W0, KIN_, nullptr, nullptr,
        nullptr, nullptr, 0, nullptr, nullptr,
        b0, nullptr, nullptr, h);

    // 4. new_tok = silu(rmsnorm(h, g0)) -> tokens slot 15
    rmsnorm_rows<<<B_ / 8, 256>>>(h, g0, tokA + 15 * D_, T_ * D_, 1);

    // 5. S4 layers (ping-pong token buffers)
    float* P = tokA;
    float* Q = tokB;
    for (int l = 0; l < L_; l++) {
        const float* nw  = norm_w    + (size_t)l * D_;
        const float* Wi  = W_in      + (size_t)l * S_ * D_;
        const float* bi  = b_in      + (size_t)l * S_;
        const float* Wo  = W_out     + (size_t)l * D_ * S_;
        const float* bo  = b_out     + (size_t)l * D_;
        const float* Ws  = W_skip    + (size_t)l * D_ * D_;
        const float* bsk = b_skip    + (size_t)l * D_;
        const float* ld  = log_decay + (size_t)l * S_;

        // a. row scales of current tokens
        scale_kernel<<<M_BIG / 8, 256>>>(P, scales);

        // b. states = scan(rmsnorm(P)@Wi^T + bi)   [fused]
        mma_gemm_scan<<<M_BIG / 64, 256, SMEM_SCAN>>>(
            P, Wi, scales, nw, bi, ld, states);

        // c. Q = states@Wo^T + bo + rmsnorm(P)@Ws^T + bsk + P
        mma_gemm<<<M_BIG / 64, 256, SMEM_GEMM>>>(
            states, Wo, S_, nullptr, nullptr,
            P, Ws, D_, scales, nw,
            bo, bsk, P, Q);

        float* tmp = P; P = Q; Q = tmp;
    }

    // 6. final rmsnorm -> output (P holds final tokens)
    rmsnorm_rows<<<M_BIG / 8, 256>>>(P, out_norm_w, out, D_, 0);
}